// round 6
// baseline (speedup 1.0000x reference)
#include <cuda_runtime.h>

#define H 8192
#define W 8192
#define KH 7
#define KW 7
#define OH (H - KH + 1)   // 8186
#define OW (W - KW + 1)   // 8186

#define TPB    128
#define RPT    16                    // rows per thread
#define TILE_X 64                    // 32 lanes * 2 cols (one f32x2 pair)
#define TILE_Y 64                    // 4 warps * 16 rows
#define SM_H   (TILE_Y + KH - 1)     // 70
#define SM_W   (TILE_X + KW - 1)     // 70
#define SP     72                    // smem pitch (floats)
#define VLEN   (RPT + KH - 1)        // 22

typedef unsigned long long u64;

__device__ __forceinline__ u64 fma2(u64 a, u64 b, u64 c) {
    u64 d;
    asm("fma.rn.f32x2 %0, %1, %2, %3;" : "=l"(d) : "l"(a), "l"(b), "l"(c));
    return d;
}
// volatile: ptxas may not rematerialize -> executes ONCE, value stays live
__device__ __forceinline__ u64 splat2v(float w) {
    u64 d;
    asm volatile("mov.b64 %0, {%1, %1};" : "=l"(d) : "f"(w));
    return d;
}
__device__ __forceinline__ u64 splat2(float w) {
    u64 d;
    asm("mov.b64 %0, {%1, %1};" : "=l"(d) : "f"(w));
    return d;
}
// {hi(a), lo(b)} — 2 register MOVs, zero L1 bytes
__device__ __forceinline__ u64 crossing(u64 a, u64 b) {
    u64 r;
    asm("{\n\t.reg .b32 al, ah, bl, bh;\n\t"
        "mov.b64 {al, ah}, %1;\n\t"
        "mov.b64 {bl, bh}, %2;\n\t"
        "mov.b64 %0, {ah, bl};\n\t}"
        : "=l"(r) : "l"(a), "l"(b));
    return r;
}

__global__ __launch_bounds__(TPB)
void conv7x7_rot3_kernel(const float* __restrict__ x,
                         const float* __restrict__ wgt,
                         const float* __restrict__ bias,
                         float* __restrict__ out)
{
    __shared__ __align__(16) float tile[SM_H * SP];
    __shared__ float wsm[KH * KW];

    const int tid  = threadIdx.x;
    const int col0 = blockIdx.x * TILE_X;
    const int row0 = blockIdx.y * TILE_Y;

    if (tid < KH * KW) wsm[tid] = wgt[tid];

    // ---- Tile fill: 70x70, clamped reads ----
    for (int idx = tid; idx < SM_H * SM_W; idx += TPB) {
        const int r = idx / SM_W;
        const int c = idx - r * SM_W;
        const int gr = min(row0 + r, H - 1);
        const int gc = min(col0 + c, W - 1);
        tile[r * SP + c] = __ldg(&x[(size_t)gr * W + gc]);
    }
    __syncthreads();

    // ---- 49 weight splats, pinned in registers via volatile asm ----
    u64 w2[KH * KW];
#pragma unroll
    for (int i = 0; i < KH * KW; i++) w2[i] = splat2v(wsm[i]);

    const int lane  = tid & 31;
    const int rbase = (tid >> 5) * RPT;       // 0,16,32,48
    const int cb    = lane * 2;               // 0..62 (u64-aligned)

    u64 acc[RPT];
#pragma unroll
    for (int o = 0; o < RPT; o++) acc[o] = 0ULL;

    const float* base = &tile[rbase * SP + cb];

    // ---- Row rotation: each input row read ONCE (4x LDS.64 = 32B),
    //      all applicable (kr,kc) weights applied to it ----
#pragma unroll
    for (int t = 0; t < VLEN; t++) {
        const u64* p = (const u64*)(base + t * SP);
        const u64 P0 = p[0];                  // cols {0,1}
        const u64 P2 = p[1];                  // cols {2,3}
        const u64 P4 = p[2];                  // cols {4,5}
        const u64 P6 = p[3];                  // cols {6,7}
        const u64 X1 = crossing(P0, P2);      // cols {1,2}
        const u64 X3 = crossing(P2, P4);      // cols {3,4}
        const u64 X5 = crossing(P4, P6);      // cols {5,6}

#pragma unroll
        for (int kr = 0; kr < KH; kr++) {
            const int o = t - kr;             // compile-time per (t,kr)
            if (o >= 0 && o < RPT) {
                u64 a = acc[o];
                a = fma2(P0, w2[kr * KW + 0], a);
                a = fma2(X1, w2[kr * KW + 1], a);
                a = fma2(P2, w2[kr * KW + 2], a);
                a = fma2(X3, w2[kr * KW + 3], a);
                a = fma2(P4, w2[kr * KW + 4], a);
                a = fma2(X5, w2[kr * KW + 5], a);
                a = fma2(P6, w2[kr * KW + 6], a);
                acc[o] = a;
            }
        }
    }

    // ---- Epilogue: bias + STG.64 (OW even: pairs never straddle) ----
    const u64 b2 = splat2(__ldg(&bias[0]));
    const int ocol = col0 + cb;
    if (ocol < OW) {
#pragma unroll
        for (int o = 0; o < RPT; o++) {
            const int orow = row0 + rbase + o;
            if (orow < OH) {
                u64 r;
                asm("add.rn.f32x2 %0, %1, %2;" : "=l"(r) : "l"(acc[o]), "l"(b2));
                *(u64*)&out[(size_t)orow * OW + ocol] = r;
            }
        }
    }
}

extern "C" void kernel_launch(void* const* d_in, const int* in_sizes, int n_in,
                              void* d_out, int out_size)
{
    const float* x    = (const float*)d_in[0];
    const float* wgt  = (const float*)d_in[1];
    const float* bias = (const float*)d_in[2];
    float* out        = (float*)d_out;

    dim3 block(TPB, 1, 1);
    dim3 grid((OW + TILE_X - 1) / TILE_X, (OH + TILE_Y - 1) / TILE_Y, 1);
    conv7x7_rot3_kernel<<<grid, block>>>(x, wgt, bias, out);
}